// round 1
// baseline (speedup 1.0000x reference)
#include <cuda_runtime.h>
#include <math.h>

#define NB 2
#define NQ 2048
#define ML 1024
#define NCTX 3072
#define DIM 1024
#define NH 16
#define DH 64

// Scratch (static __device__ to satisfy no-allocation rule)
__device__ float g_Q[NB * NQ * DIM];                 // 16 MB
__device__ float g_CTX[NB * NCTX * DIM];             // 24 MB
__device__ float g_KV[(size_t)NB * NCTX * 2 * DIM];  // 48 MB
__device__ float g_POS[NQ * DH];                     // 0.5 MB
__device__ float g_O[NB * NQ * DIM];                 // 16 MB

// ---------------------------------------------------------------------------
// Build context = concat(mem, x) along seq dim
// ---------------------------------------------------------------------------
__global__ void build_ctx(const float* __restrict__ x, const float* __restrict__ mem) {
    int idx = blockIdx.x * 256 + threadIdx.x;
    const int per = DIM / 4;
    if (idx >= NB * NCTX * per) return;
    int d4 = idx % per;
    int t_idx = idx / per;
    int b = t_idx / NCTX, t = t_idx % NCTX;
    float4 v;
    if (t < ML) v = ((const float4*)mem)[(b * ML + t) * per + d4];
    else        v = ((const float4*)x)[(b * NQ + (t - ML)) * per + d4];
    ((float4*)g_CTX)[idx] = v;
}

// ---------------------------------------------------------------------------
// Generic fp32 tiled GEMM: C[M,N] = A[M,K] @ B[K,N] + bias[N]
// BM=BN=128, BK=16, 256 threads, 8x8 per thread.
// M % 128 == 0 and K % 16 == 0 assumed (true for all calls). N guarded.
// ---------------------------------------------------------------------------
__device__ __forceinline__ void sgemm_body(const float* __restrict__ A,
                                           const float* __restrict__ Bm,
                                           const float* __restrict__ bias,
                                           float* __restrict__ C,
                                           int M, int N, int K) {
    __shared__ float As[16][128];
    __shared__ float Bs[16][128];
    int n0 = blockIdx.x * 128, m0 = blockIdx.y * 128;
    int tid = threadIdx.x;
    int tx = tid & 15, ty = tid >> 4;
    float acc[8][8] = {};
    for (int k0 = 0; k0 < K; k0 += 16) {
#pragma unroll
        for (int i = 0; i < 2; i++) {
            int idx = tid + i * 256;
            int row = idx >> 2, kq = (idx & 3) << 2;
            float4 a = *(const float4*)&A[(size_t)(m0 + row) * K + k0 + kq];
            As[kq + 0][row] = a.x; As[kq + 1][row] = a.y;
            As[kq + 2][row] = a.z; As[kq + 3][row] = a.w;
        }
#pragma unroll
        for (int i = 0; i < 2; i++) {
            int idx = tid + i * 256;
            int row = idx >> 5, c4 = (idx & 31) << 2;
            float4 bv = make_float4(0.f, 0.f, 0.f, 0.f);
            if (n0 + c4 < N) bv = *(const float4*)&Bm[(size_t)(k0 + row) * N + n0 + c4];
            *(float4*)&Bs[row][c4] = bv;
        }
        __syncthreads();
#pragma unroll
        for (int k = 0; k < 16; k++) {
            float a[8], bb[8];
            *(float4*)&a[0] = *(const float4*)&As[k][ty * 8];
            *(float4*)&a[4] = *(const float4*)&As[k][ty * 8 + 4];
            *(float4*)&bb[0] = *(const float4*)&Bs[k][tx * 8];
            *(float4*)&bb[4] = *(const float4*)&Bs[k][tx * 8 + 4];
#pragma unroll
            for (int r = 0; r < 8; r++)
#pragma unroll
                for (int c = 0; c < 8; c++)
                    acc[r][c] += a[r] * bb[c];
        }
        __syncthreads();
    }
#pragma unroll
    for (int r = 0; r < 8; r++) {
        int m = m0 + ty * 8 + r;
#pragma unroll
        for (int c = 0; c < 8; c++) {
            int n = n0 + tx * 8 + c;
            if (n < N) C[(size_t)m * N + n] = acc[r][c] + bias[n];
        }
    }
}

__global__ void __launch_bounds__(256) gemm_q(const float* x, const float* Wq, const float* bq) {
    sgemm_body(x, Wq, bq, g_Q, NB * NQ, DIM, DIM);
}
__global__ void __launch_bounds__(256) gemm_kv(const float* Wkv, const float* bkv) {
    sgemm_body(g_CTX, Wkv, bkv, g_KV, NB * NCTX, 2 * DIM, DIM);
}
__global__ void __launch_bounds__(256) gemm_pos(const float* pe, const float* Wp, const float* bp) {
    sgemm_body(pe, Wp, bp, g_POS, NQ, DH, DIM);
}
__global__ void __launch_bounds__(256) gemm_out(const float* Wo, const float* bo, float* out) {
    sgemm_body(g_O, Wo, bo, out, NB * NQ, DIM, DIM);
}

// ---------------------------------------------------------------------------
// Flash-style attention with Transformer-XL relative position ring buffer.
// Grid: (32 q-tiles, 32 b*h). Block: 256 threads (16x16), 4x4 per thread.
// Dynamic smem: Qs[64*64] | PD[64*128] | bufA[64*64] (K/V) | bufB[64*64] (pos/P)
// smem tiles for K/V/pos use XOR swizzle: phys float4 slot = slot ^ (row>>2).
// ---------------------------------------------------------------------------
__global__ void __launch_bounds__(256) attn_kernel(const float* __restrict__ em) {
    extern __shared__ float smp[];
    float* Qs   = smp;             // 4096 floats
    float* PD   = smp + 4096;      // 8192 floats (64 rows x 128 ring cols)
    float* bufA = smp + 12288;     // 4096 floats
    float* bufB = smp + 16384;     // 4096 floats
    int bh = blockIdx.y;
    int b = bh >> 4, h = bh & 15;
    int qt = blockIdx.x;
    int i0 = qt * 64;
    int tid = threadIdx.x;
    int tx = tid & 15, ty = tid >> 4;
    const float scale = 0.125f;  // dh^-0.5, dh=64

    // load Q tile (prescaled by `scale` — applies to both content and pos dots)
    for (int i = tid; i < 1024; i += 256) {
        int r = i >> 4, s4 = (i & 15) << 2;
        float4 q = *(const float4*)&g_Q[(size_t)(b * NQ + i0 + r) * DIM + h * DH + s4];
        q.x *= scale; q.y *= scale; q.z *= scale; q.w *= scale;
        *(float4*)&Qs[r * 64 + s4] = q;
    }

    float m_r[4], l_r[4], O[4][4];
#pragma unroll
    for (int rr = 0; rr < 4; rr++) {
        m_r[rr] = -1e30f; l_r[rr] = 0.f;
#pragma unroll
        for (int cc = 0; cc < 4; cc++) O[rr][cc] = 0.f;
    }

    int nT = 17 + qt;  // key tiles: mem (16) + causal part of current (qt+1)
    for (int jt = 0; jt < nT; jt++) {
        int J0 = jt * 64;
        __syncthreads();  // prev-iteration bufA(V)/bufB(P) fully consumed
        // ---- load K tile (swizzled rows) ----
        for (int i = tid; i < 1024; i += 256) {
            int c = i >> 4, slot = i & 15;
            float4 v = *(const float4*)&g_KV[(size_t)(b * NCTX + J0 + c) * 2048 + h * DH + (slot << 2)];
            *(float4*)&bufA[c * 64 + ((slot ^ (c >> 2)) << 2)] = v;
        }
        __syncthreads();

        int Pbase = 0;
        if (jt >= 16) {
            // ---- compute new columns of the PD ring: PD[r][p&127] = q_r . pos_p ----
            int j0l = J0 - ML;
            Pbase = NQ - 64 - i0 + j0l;  // window start; needed p in [Pbase, Pbase+126]
            int nNew = (jt == 16) ? 2 : 1;
            int Pst  = (jt == 16) ? Pbase : Pbase + 64;
            for (int half = 0; half < nNew; half++) {
                int Pn = Pst + half * 64;
                for (int i = tid; i < 1024; i += 256) {
                    int s = i >> 4, slot = i & 15;
                    int p = Pn + s;
                    float4 v = make_float4(0.f, 0.f, 0.f, 0.f);
                    if (p < NQ) v = *(const float4*)&g_POS[p * DH + (slot << 2)];
                    *(float4*)&bufB[s * 64 + ((slot ^ (s >> 2)) << 2)] = v;
                }
                __syncthreads();
                float pd[4][4] = {};
#pragma unroll
                for (int d4 = 0; d4 < 16; d4++) {
                    float4 q4[4], p4[4];
#pragma unroll
                    for (int rr = 0; rr < 4; rr++)
                        q4[rr] = *(const float4*)&Qs[(ty * 4 + rr) * 64 + (d4 << 2)];
                    int sl = (d4 ^ tx) << 2;
#pragma unroll
                    for (int ss = 0; ss < 4; ss++)
                        p4[ss] = *(const float4*)&bufB[(tx * 4 + ss) * 64 + sl];
#pragma unroll
                    for (int rr = 0; rr < 4; rr++)
#pragma unroll
                        for (int ss = 0; ss < 4; ss++)
                            pd[rr][ss] += q4[rr].x * p4[ss].x + q4[rr].y * p4[ss].y
                                        + q4[rr].z * p4[ss].z + q4[rr].w * p4[ss].w;
                }
#pragma unroll
                for (int rr = 0; rr < 4; rr++)
#pragma unroll
                    for (int ss = 0; ss < 4; ss++)
                        PD[(ty * 4 + rr) * 128 + ((Pn + tx * 4 + ss) & 127)] = pd[rr][ss];
                __syncthreads();
            }
        }

        // ---- scores S = (scaled q) . k  (+ PD diagonal lookup, mask) ----
        float S[4][4] = {};
#pragma unroll
        for (int d4 = 0; d4 < 16; d4++) {
            float4 q4[4], k4[4];
#pragma unroll
            for (int rr = 0; rr < 4; rr++)
                q4[rr] = *(const float4*)&Qs[(ty * 4 + rr) * 64 + (d4 << 2)];
            int sl = (d4 ^ tx) << 2;
#pragma unroll
            for (int cc = 0; cc < 4; cc++)
                k4[cc] = *(const float4*)&bufA[(tx * 4 + cc) * 64 + sl];
#pragma unroll
            for (int rr = 0; rr < 4; rr++)
#pragma unroll
                for (int cc = 0; cc < 4; cc++)
                    S[rr][cc] += q4[rr].x * k4[cc].x + q4[rr].y * k4[cc].y
                               + q4[rr].z * k4[cc].z + q4[rr].w * k4[cc].w;
        }

        float emv[4] = {1.f, 1.f, 1.f, 1.f};
        if (jt < 16) {
            // memory region: expire mask, no pos term, never causally masked
#pragma unroll
            for (int cc = 0; cc < 4; cc++)
                emv[cc] = em[b * ML + J0 + tx * 4 + cc];
        } else {
            int j0l = J0 - ML;
#pragma unroll
            for (int rr = 0; rr < 4; rr++) {
                int r = ty * 4 + rr;
#pragma unroll
                for (int cc = 0; cc < 4; cc++) {
                    int c = tx * 4 + cc;
                    S[rr][cc] += PD[r * 128 + ((Pbase + 63 + c - r) & 127)];
                    if (j0l + c > i0 + r) S[rr][cc] = -1e10f;
                }
            }
        }

        // ---- online softmax (row stats across 16 lanes, width-16 shuffles) ----
#pragma unroll
        for (int rr = 0; rr < 4; rr++) {
            float mx = fmaxf(fmaxf(S[rr][0], S[rr][1]), fmaxf(S[rr][2], S[rr][3]));
#pragma unroll
            for (int off = 1; off < 16; off <<= 1)
                mx = fmaxf(mx, __shfl_xor_sync(0xffffffffu, mx, off, 16));
            float mnew = fmaxf(m_r[rr], mx);
            float alpha = __expf(m_r[rr] - mnew);
            float rs = 0.f;
#pragma unroll
            for (int cc = 0; cc < 4; cc++) {
                float e = __expf(S[rr][cc] - mnew);
                rs += e;                 // denominator WITHOUT expire mask
                S[rr][cc] = e * emv[cc]; // numerator WITH expire mask
            }
#pragma unroll
            for (int off = 1; off < 16; off <<= 1)
                rs += __shfl_xor_sync(0xffffffffu, rs, off, 16);
            l_r[rr] = l_r[rr] * alpha + rs;
            m_r[rr] = mnew;
#pragma unroll
            for (int cc = 0; cc < 4; cc++) O[rr][cc] *= alpha;
#pragma unroll
            for (int cc = 0; cc < 4; cc++)
                bufB[(ty * 4 + rr) * 64 + tx * 4 + cc] = S[rr][cc];  // P tile
        }
        __syncthreads();  // P complete, K fully consumed

        // ---- load V tile (swizzled) ----
        for (int i = tid; i < 1024; i += 256) {
            int c = i >> 4, slot = i & 15;
            float4 v = *(const float4*)&g_KV[(size_t)(b * NCTX + J0 + c) * 2048 + DIM + h * DH + (slot << 2)];
            *(float4*)&bufA[c * 64 + ((slot ^ (c >> 2)) << 2)] = v;
        }
        __syncthreads();

        // ---- O += P @ V ----
#pragma unroll
        for (int c4 = 0; c4 < 16; c4++) {
            float4 p4[4], v4[4];
#pragma unroll
            for (int rr = 0; rr < 4; rr++)
                p4[rr] = *(const float4*)&bufB[(ty * 4 + rr) * 64 + (c4 << 2)];
            int sl = (tx ^ c4) << 2;
#pragma unroll
            for (int k = 0; k < 4; k++)
                v4[k] = *(const float4*)&bufA[(c4 * 4 + k) * 64 + sl];
#pragma unroll
            for (int rr = 0; rr < 4; rr++) {
                O[rr][0] += p4[rr].x * v4[0].x + p4[rr].y * v4[1].x + p4[rr].z * v4[2].x + p4[rr].w * v4[3].x;
                O[rr][1] += p4[rr].x * v4[0].y + p4[rr].y * v4[1].y + p4[rr].z * v4[2].y + p4[rr].w * v4[3].y;
                O[rr][2] += p4[rr].x * v4[0].z + p4[rr].y * v4[1].z + p4[rr].z * v4[2].z + p4[rr].w * v4[3].z;
                O[rr][3] += p4[rr].x * v4[0].w + p4[rr].y * v4[1].w + p4[rr].z * v4[2].w + p4[rr].w * v4[3].w;
            }
        }
    }

    // ---- finalize: divide by softmax denominator, write merged-head layout ----
#pragma unroll
    for (int rr = 0; rr < 4; rr++) {
        float inv = 1.0f / l_r[rr];
        float4 o4 = make_float4(O[rr][0] * inv, O[rr][1] * inv, O[rr][2] * inv, O[rr][3] * inv);
        *(float4*)&g_O[(size_t)(b * NQ + i0 + ty * 4 + rr) * DIM + h * DH + tx * 4] = o4;
    }
}

// ---------------------------------------------------------------------------
extern "C" void kernel_launch(void* const* d_in, const int* in_sizes, int n_in,
                              void* d_out, int out_size) {
    const float* x   = (const float*)d_in[0];
    const float* pe  = (const float*)d_in[1];
    const float* mem = (const float*)d_in[2];
    const float* em  = (const float*)d_in[3];
    const float* Wq  = (const float*)d_in[4];
    const float* bq  = (const float*)d_in[5];
    const float* Wkv = (const float*)d_in[6];
    const float* bkv = (const float*)d_in[7];
    const float* Wo  = (const float*)d_in[8];
    const float* bo  = (const float*)d_in[9];
    const float* Wp  = (const float*)d_in[10];
    const float* bp  = (const float*)d_in[11];
    float* out = (float*)d_out;

    build_ctx<<<(NB * NCTX * (DIM / 4) + 255) / 256, 256>>>(x, mem);
    gemm_q<<<dim3(8, 32), 256>>>(x, Wq, bq);
    gemm_kv<<<dim3(16, 48), 256>>>(Wkv, bkv);
    gemm_pos<<<dim3(1, 16), 256>>>(pe, Wp, bp);
    // 80 KB dynamic smem (Qs 16K + PD 32K + bufA 16K + bufB 16K)
    cudaFuncSetAttribute(attn_kernel, cudaFuncAttributeMaxDynamicSharedMemorySize, 81920);
    attn_kernel<<<dim3(32, 32), 256, 81920>>>(em);
    gemm_out<<<dim3(8, 32), 256>>>(Wo, bo, out);
}

// round 2
// speedup vs baseline: 2.6177x; 2.6177x over previous
#include <cuda_runtime.h>
#include <math.h>

#define NB 2
#define NQ 2048
#define ML 1024
#define NCTX 3072
#define DIM 1024
#define NH 16
#define DH 64

// Scratch (static __device__ to satisfy no-allocation rule)
__device__ float g_Q[NB * NQ * DIM];
__device__ float g_CTX[NB * NCTX * DIM];
__device__ float g_KV[(size_t)NB * NCTX * 2 * DIM];
__device__ float g_POS[NQ * DH];
__device__ float g_O[NB * NQ * DIM];

// ---------------------------------------------------------------------------
__device__ __forceinline__ unsigned f2tf(float f) {
    unsigned u;
    asm("cvt.rna.tf32.f32 %0, %1;" : "=r"(u) : "f"(f));
    return u;
}

__device__ __forceinline__ void mma8(float* c, const unsigned* a, const unsigned* b) {
    asm volatile(
        "mma.sync.aligned.m16n8k8.row.col.f32.tf32.tf32.f32 "
        "{%0,%1,%2,%3}, {%4,%5,%6,%7}, {%8,%9}, {%0,%1,%2,%3};\n"
        : "+f"(c[0]), "+f"(c[1]), "+f"(c[2]), "+f"(c[3])
        : "r"(a[0]), "r"(a[1]), "r"(a[2]), "r"(a[3]), "r"(b[0]), "r"(b[1]));
}

// ---------------------------------------------------------------------------
__global__ void build_ctx(const float* __restrict__ x, const float* __restrict__ mem) {
    int idx = blockIdx.x * 256 + threadIdx.x;
    const int per = DIM / 4;
    if (idx >= NB * NCTX * per) return;
    int d4 = idx % per;
    int t_idx = idx / per;
    int b = t_idx / NCTX, t = t_idx % NCTX;
    float4 v;
    if (t < ML) v = ((const float4*)mem)[(b * ML + t) * per + d4];
    else        v = ((const float4*)x)[(b * NQ + (t - ML)) * per + d4];
    ((float4*)g_CTX)[idx] = v;
}

// ---------------------------------------------------------------------------
// TF32 tensor-core GEMM: C[M,N] = A[M,K] @ B[K,N] + bias[N]
// 128x128x32 tiles, 256 threads = 8 warps (2 m x 4 n), each warp 64x32.
// M%128==0, K%32==0 assumed; N guarded.
// ---------------------------------------------------------------------------
__device__ __forceinline__ void mma_gemm(const float* __restrict__ A,
                                         const float* __restrict__ B,
                                         const float* __restrict__ bias,
                                         float* __restrict__ C,
                                         int M, int N, int K) {
    __shared__ unsigned As[128][36];
    __shared__ unsigned Bs[32][132];
    const int tid = threadIdx.x;
    const int m0 = blockIdx.y * 128, n0 = blockIdx.x * 128;
    const int lane = tid & 31, wid = tid >> 5;
    const int wm = wid & 1, wn = wid >> 1;
    const int gid = lane >> 2, tig = lane & 3;
    float acc[4][4][4] = {};
    for (int k0 = 0; k0 < K; k0 += 32) {
#pragma unroll
        for (int i = 0; i < 4; i++) {
            int idx = tid + i * 256;
            int r = idx >> 3, c4 = (idx & 7) << 2;
            float4 v = *(const float4*)&A[(size_t)(m0 + r) * K + k0 + c4];
            *(uint4*)&As[r][c4] = make_uint4(f2tf(v.x), f2tf(v.y), f2tf(v.z), f2tf(v.w));
        }
#pragma unroll
        for (int i = 0; i < 4; i++) {
            int idx = tid + i * 256;
            int r = idx >> 5, c4 = (idx & 31) << 2;
            float4 v = make_float4(0.f, 0.f, 0.f, 0.f);
            if (n0 + c4 < N) v = *(const float4*)&B[(size_t)(k0 + r) * N + n0 + c4];
            *(uint4*)&Bs[r][c4] = make_uint4(f2tf(v.x), f2tf(v.y), f2tf(v.z), f2tf(v.w));
        }
        __syncthreads();
#pragma unroll
        for (int kk = 0; kk < 4; kk++) {
            const int kb = kk * 8;
            unsigned a[4][4], bf[4][2];
#pragma unroll
            for (int mt = 0; mt < 4; mt++) {
                int r = wm * 64 + mt * 16 + gid;
                a[mt][0] = As[r][kb + tig];     a[mt][1] = As[r + 8][kb + tig];
                a[mt][2] = As[r][kb + tig + 4]; a[mt][3] = As[r + 8][kb + tig + 4];
            }
#pragma unroll
            for (int nt = 0; nt < 4; nt++) {
                int c = wn * 32 + nt * 8 + gid;
                bf[nt][0] = Bs[kb + tig][c]; bf[nt][1] = Bs[kb + tig + 4][c];
            }
#pragma unroll
            for (int mt = 0; mt < 4; mt++)
#pragma unroll
                for (int nt = 0; nt < 4; nt++) mma8(acc[mt][nt], a[mt], bf[nt]);
        }
        __syncthreads();
    }
#pragma unroll
    for (int mt = 0; mt < 4; mt++) {
        int r0 = m0 + wm * 64 + mt * 16 + gid;
#pragma unroll
        for (int nt = 0; nt < 4; nt++) {
            int c0 = n0 + wn * 32 + nt * 8 + 2 * tig;
            if (c0 < N) {
                C[(size_t)r0 * N + c0]           = acc[mt][nt][0] + bias[c0];
                C[(size_t)r0 * N + c0 + 1]       = acc[mt][nt][1] + bias[c0 + 1];
                C[(size_t)(r0 + 8) * N + c0]     = acc[mt][nt][2] + bias[c0];
                C[(size_t)(r0 + 8) * N + c0 + 1] = acc[mt][nt][3] + bias[c0 + 1];
            }
        }
    }
}

__global__ void __launch_bounds__(256) gemm_q(const float* x, const float* Wq, const float* bq) {
    mma_gemm(x, Wq, bq, g_Q, NB * NQ, DIM, DIM);
}
__global__ void __launch_bounds__(256) gemm_kv(const float* Wkv, const float* bkv) {
    mma_gemm(g_CTX, Wkv, bkv, g_KV, NB * NCTX, 2 * DIM, DIM);
}
__global__ void __launch_bounds__(256) gemm_pos(const float* pe, const float* Wp, const float* bp) {
    mma_gemm(pe, Wp, bp, g_POS, NQ, DH, DIM);
}
__global__ void __launch_bounds__(256) gemm_out(const float* Wo, const float* bo, float* out) {
    mma_gemm(g_O, Wo, bo, out, NB * NQ, DIM, DIM);
}

// ---------------------------------------------------------------------------
// Flash attention + Transformer-XL relative position, tensor-core tf32 mma.
// Block: 128 threads (4 warps), 64-row q-tile per block; warp w owns rows
// [16w,16w+16). Grid (32 qtiles reversed, 32 b*h).
// smem: Qs | Ks(K then V) | PB(pos then P) : 64x68 tf32 each; PD ring 64x132
// fp32; em_s 1024 fp32. 90112 bytes -> 2 CTAs/SM.
// ---------------------------------------------------------------------------
#define SQ 68
#define SPD 132
#define ATTN_SMEM ((3 * 64 * SQ + 64 * SPD + 1024) * 4)

__global__ void __launch_bounds__(128) attn_kernel(const float* __restrict__ em) {
    extern __shared__ unsigned sm[];
    unsigned* Qs = sm;
    unsigned* Ks = sm + 64 * SQ;
    unsigned* PB = sm + 2 * 64 * SQ;
    float* PD    = (float*)(sm + 3 * 64 * SQ);
    float* em_s  = (float*)(sm + 3 * 64 * SQ + 64 * SPD);

    const int bh = blockIdx.y;
    const int b = bh >> 4, h = bh & 15;
    const int qt = 31 - blockIdx.x;
    const int i0 = qt * 64;
    const int tid = threadIdx.x;
    const int lane = tid & 31, wid = tid >> 5;
    const int gid = lane >> 2, tig = lane & 3;
    const int r1 = wid * 16 + gid, r2 = r1 + 8;

    for (int i = tid; i < ML / 4; i += 128)
        ((float4*)em_s)[i] = ((const float4*)(em + b * ML))[i];

    for (int i = tid; i < 1024; i += 128) {
        int r = i >> 4, c4 = (i & 15) << 2;
        float4 v = *(const float4*)&g_Q[(size_t)(b * NQ + i0 + r) * DIM + h * DH + c4];
        *(uint4*)&Qs[r * SQ + c4] = make_uint4(
            f2tf(v.x * 0.125f), f2tf(v.y * 0.125f), f2tf(v.z * 0.125f), f2tf(v.w * 0.125f));
    }

    float m1 = -1e30f, m2 = -1e30f, l1 = 0.f, l2 = 0.f;
    float O[8][4] = {};

    const int nT = 17 + qt;
    int Pbase = 0;
    for (int jt = 0; jt < nT; jt++) {
        const int J0 = jt * 64;
        __syncthreads();  // prev tile's V / P fully consumed
        // ---- K tile ----
        for (int i = tid; i < 1024; i += 128) {
            int r = i >> 4, c4 = (i & 15) << 2;
            float4 v = *(const float4*)&g_KV[(size_t)(b * NCTX + J0 + r) * (2 * DIM) + h * DH + c4];
            *(uint4*)&Ks[r * SQ + c4] = make_uint4(f2tf(v.x), f2tf(v.y), f2tf(v.z), f2tf(v.w));
        }
        if (jt >= 16) {
            // ---- extend PD ring: PD[r][p&127] = q_r . pos_p (scaled) ----
            const int j0l = J0 - ML;
            Pbase = NQ - 64 - i0 + j0l;
            const int nNew = (jt == 16) ? 2 : 1;
            const int Pst = (jt == 16) ? Pbase : Pbase + 64;
            for (int half = 0; half < nNew; half++) {
                const int Pn = Pst + half * 64;
                if (half) __syncthreads();
                for (int i = tid; i < 1024; i += 128) {
                    int s = i >> 4, c4 = (i & 15) << 2;
                    int p = Pn + s;
                    float4 v = make_float4(0.f, 0.f, 0.f, 0.f);
                    if (p < NQ) v = *(const float4*)&g_POS[p * DH + c4];
                    *(uint4*)&PB[s * SQ + c4] = make_uint4(f2tf(v.x), f2tf(v.y), f2tf(v.z), f2tf(v.w));
                }
                __syncthreads();
                float pd[8][4] = {};
#pragma unroll
                for (int kk = 0; kk < 8; kk++) {
                    const int kb = kk * 8;
                    unsigned a[4];
                    a[0] = Qs[r1 * SQ + kb + tig];     a[1] = Qs[r2 * SQ + kb + tig];
                    a[2] = Qs[r1 * SQ + kb + tig + 4]; a[3] = Qs[r2 * SQ + kb + tig + 4];
#pragma unroll
                    for (int nt = 0; nt < 8; nt++) {
                        unsigned bf[2];
                        const int c = nt * 8 + gid;
                        bf[0] = PB[c * SQ + kb + tig]; bf[1] = PB[c * SQ + kb + tig + 4];
                        mma8(pd[nt], a, bf);
                    }
                }
#pragma unroll
                for (int nt = 0; nt < 8; nt++) {
                    const int cb = nt * 8 + 2 * tig;
                    PD[r1 * SPD + ((Pn + cb) & 127)]     = pd[nt][0];
                    PD[r1 * SPD + ((Pn + cb + 1) & 127)] = pd[nt][1];
                    PD[r2 * SPD + ((Pn + cb) & 127)]     = pd[nt][2];
                    PD[r2 * SPD + ((Pn + cb + 1) & 127)] = pd[nt][3];
                }
            }
        }
        __syncthreads();  // K (and PD ring extension) ready

        // ---- S = Q K^T ----
        float S[8][4] = {};
#pragma unroll
        for (int kk = 0; kk < 8; kk++) {
            const int kb = kk * 8;
            unsigned a[4];
            a[0] = Qs[r1 * SQ + kb + tig];     a[1] = Qs[r2 * SQ + kb + tig];
            a[2] = Qs[r1 * SQ + kb + tig + 4]; a[3] = Qs[r2 * SQ + kb + tig + 4];
#pragma unroll
            for (int nt = 0; nt < 8; nt++) {
                unsigned bf[2];
                const int c = nt * 8 + gid;
                bf[0] = Ks[c * SQ + kb + tig]; bf[1] = Ks[c * SQ + kb + tig + 4];
                mma8(S[nt], a, bf);
            }
        }
        __syncthreads();  // Ks consumed -> reload as V; PB consumed -> reuse as P

        // ---- V tile into Ks buffer (overlaps softmax below) ----
        for (int i = tid; i < 1024; i += 128) {
            int r = i >> 4, c4 = (i & 15) << 2;
            float4 v = *(const float4*)&g_KV[(size_t)(b * NCTX + J0 + r) * (2 * DIM) + DIM + h * DH + c4];
            *(uint4*)&Ks[r * SQ + c4] = make_uint4(f2tf(v.x), f2tf(v.y), f2tf(v.z), f2tf(v.w));
        }

        // ---- pos/mask or expire prep ----
        const bool memr = (jt < 16);
        float emv[8][2];
        if (memr) {
#pragma unroll
            for (int nt = 0; nt < 8; nt++) {
                const int cb = nt * 8 + 2 * tig;
                emv[nt][0] = em_s[J0 + cb]; emv[nt][1] = em_s[J0 + cb + 1];
            }
        } else {
            const int j0l = J0 - ML;
#pragma unroll
            for (int nt = 0; nt < 8; nt++) {
                const int cb = nt * 8 + 2 * tig;
                S[nt][0] += PD[r1 * SPD + ((Pbase + 63 + cb - r1) & 127)];
                S[nt][1] += PD[r1 * SPD + ((Pbase + 64 + cb - r1) & 127)];
                S[nt][2] += PD[r2 * SPD + ((Pbase + 63 + cb - r2) & 127)];
                S[nt][3] += PD[r2 * SPD + ((Pbase + 64 + cb - r2) & 127)];
                if (j0l + cb > i0 + r1)     S[nt][0] = -1e10f;
                if (j0l + cb + 1 > i0 + r1) S[nt][1] = -1e10f;
                if (j0l + cb > i0 + r2)     S[nt][2] = -1e10f;
                if (j0l + cb + 1 > i0 + r2) S[nt][3] = -1e10f;
            }
        }

        // ---- online softmax (rows r1, r2 per thread; quad shuffles) ----
        float mx1 = -1e30f, mx2 = -1e30f;
#pragma unroll
        for (int nt = 0; nt < 8; nt++) {
            mx1 = fmaxf(mx1, fmaxf(S[nt][0], S[nt][1]));
            mx2 = fmaxf(mx2, fmaxf(S[nt][2], S[nt][3]));
        }
        mx1 = fmaxf(mx1, __shfl_xor_sync(0xffffffffu, mx1, 1));
        mx1 = fmaxf(mx1, __shfl_xor_sync(0xffffffffu, mx1, 2));
        mx2 = fmaxf(mx2, __shfl_xor_sync(0xffffffffu, mx2, 1));
        mx2 = fmaxf(mx2, __shfl_xor_sync(0xffffffffu, mx2, 2));
        const float mn1 = fmaxf(m1, mx1), mn2 = fmaxf(m2, mx2);
        const float al1 = __expf(m1 - mn1), al2 = __expf(m2 - mn2);
        float rs1 = 0.f, rs2 = 0.f;
#pragma unroll
        for (int nt = 0; nt < 8; nt++) {
            float e0 = __expf(S[nt][0] - mn1), e1 = __expf(S[nt][1] - mn1);
            float e2 = __expf(S[nt][2] - mn2), e3 = __expf(S[nt][3] - mn2);
            rs1 += e0 + e1; rs2 += e2 + e3;
            if (memr) { e0 *= emv[nt][0]; e1 *= emv[nt][1]; e2 *= emv[nt][0]; e3 *= emv[nt][1]; }
            const int cb = nt * 8 + 2 * tig;
            PB[r1 * SQ + cb] = f2tf(e0); PB[r1 * SQ + cb + 1] = f2tf(e1);
            PB[r2 * SQ + cb] = f2tf(e2); PB[r2 * SQ + cb + 1] = f2tf(e3);
        }
        rs1 += __shfl_xor_sync(0xffffffffu, rs1, 1);
        rs1 += __shfl_xor_sync(0xffffffffu, rs1, 2);
        rs2 += __shfl_xor_sync(0xffffffffu, rs2, 1);
        rs2 += __shfl_xor_sync(0xffffffffu, rs2, 2);
        m1 = mn1; m2 = mn2;
        l1 = l1 * al1 + rs1; l2 = l2 * al2 + rs2;
#pragma unroll
        for (int nt = 0; nt < 8; nt++) {
            O[nt][0] *= al1; O[nt][1] *= al1; O[nt][2] *= al2; O[nt][3] *= al2;
        }
        __syncthreads();  // V loaded, P written (cross-lane) -> PV

        // ---- O += P @ V ----
#pragma unroll
        for (int kk = 0; kk < 8; kk++) {
            const int kb = kk * 8;
            unsigned a[4];
            a[0] = PB[r1 * SQ + kb + tig];     a[1] = PB[r2 * SQ + kb + tig];
            a[2] = PB[r1 * SQ + kb + tig + 4]; a[3] = PB[r2 * SQ + kb + tig + 4];
#pragma unroll
            for (int nt = 0; nt < 8; nt++) {
                unsigned bf[2];
                const int c = nt * 8 + gid;
                bf[0] = Ks[(kb + tig) * SQ + c]; bf[1] = Ks[(kb + tig + 4) * SQ + c];
                mma8(O[nt], a, bf);
            }
        }
    }

    // ---- finalize ----
    const float inv1 = 1.f / l1, inv2 = 1.f / l2;
#pragma unroll
    for (int nt = 0; nt < 8; nt++) {
        const int d = h * DH + nt * 8 + 2 * tig;
        float* o1 = &g_O[(size_t)(b * NQ + i0 + r1) * DIM + d];
        float* o2 = &g_O[(size_t)(b * NQ + i0 + r2) * DIM + d];
        o1[0] = O[nt][0] * inv1; o1[1] = O[nt][1] * inv1;
        o2[0] = O[nt][2] * inv2; o2[1] = O[nt][3] * inv2;
    }
}

// ---------------------------------------------------------------------------
extern "C" void kernel_launch(void* const* d_in, const int* in_sizes, int n_in,
                              void* d_out, int out_size) {
    const float* x   = (const float*)d_in[0];
    const float* pe  = (const float*)d_in[1];
    const float* mem = (const float*)d_in[2];
    const float* em  = (const float*)d_in[3];
    const float* Wq  = (const float*)d_in[4];
    const float* bq  = (const float*)d_in[5];
    const float* Wkv = (const float*)d_in[6];
    const float* bkv = (const float*)d_in[7];
    const float* Wo  = (const float*)d_in[8];
    const float* bo  = (const float*)d_in[9];
    const float* Wp  = (const float*)d_in[10];
    const float* bp  = (const float*)d_in[11];
    float* out = (float*)d_out;

    build_ctx<<<(NB * NCTX * (DIM / 4) + 255) / 256, 256>>>(x, mem);
    gemm_q<<<dim3(8, 32), 256>>>(x, Wq, bq);
    gemm_kv<<<dim3(16, 48), 256>>>(Wkv, bkv);
    gemm_pos<<<dim3(1, 16), 256>>>(pe, Wp, bp);
    cudaFuncSetAttribute(attn_kernel, cudaFuncAttributeMaxDynamicSharedMemorySize, ATTN_SMEM);
    attn_kernel<<<dim3(32, 32), 128, ATTN_SMEM>>>(em);
    gemm_out<<<dim3(8, 32), 256>>>(Wo, bo, out);
}

// round 3
// speedup vs baseline: 3.0828x; 1.1777x over previous
#include <cuda_runtime.h>

#define NB 2
#define NQ 2048
#define ML 1024
#define NCTX 3072
#define DIM 1024
#define NH 16
#define DH 64

// Scratch (static __device__ to satisfy no-allocation rule)
__device__ float g_Q[NB * NQ * DIM];
__device__ float g_KV[(size_t)NB * NCTX * 2 * DIM];
__device__ float g_POS[NQ * DH];
__device__ float g_PPART[8 * NQ * DH];
__device__ float g_O[NB * NQ * DIM];

// ---------------------------------------------------------------------------
__device__ __forceinline__ unsigned f2tf(float f) {
    unsigned u;
    asm("cvt.rna.tf32.f32 %0, %1;" : "=r"(u) : "f"(f));
    return u;
}

__device__ __forceinline__ void mma8(float* c, const unsigned* a, const unsigned* b) {
    asm volatile(
        "mma.sync.aligned.m16n8k8.row.col.f32.tf32.tf32.f32 "
        "{%0,%1,%2,%3}, {%4,%5,%6,%7}, {%8,%9}, {%0,%1,%2,%3};\n"
        : "+f"(c[0]), "+f"(c[1]), "+f"(c[2]), "+f"(c[3])
        : "r"(a[0]), "r"(a[1]), "r"(a[2]), "r"(a[3]), "r"(b[0]), "r"(b[1]));
}

__device__ __forceinline__ unsigned s2u(const void* p) {
    unsigned r;
    asm("{ .reg .u64 t; cvta.to.shared.u64 t, %1; cvt.u32.u64 %0, t; }" : "=r"(r) : "l"(p));
    return r;
}
__device__ __forceinline__ void cpa16(unsigned saddr, const void* g) {
    asm volatile("cp.async.cg.shared.global [%0], [%1], 16;\n" :: "r"(saddr), "l"(g));
}
__device__ __forceinline__ void cpa_commit() { asm volatile("cp.async.commit_group;\n"); }
template <int N>
__device__ __forceinline__ void cpa_wait() { asm volatile("cp.async.wait_group %0;\n" :: "n"(N)); }

// ---------------------------------------------------------------------------
// TF32 tensor-core GEMM with 2-stage cp.async pipeline.
// C[M,N] = A[M,K] @ B[K,N] + bias[N]. 128x128x32 tiles, 256 threads.
// All callers have N % 128 == 0, M % 128 == 0, K % 32 == 0 (no guards).
// CTX mode: A row m maps to concat(mem, x) per batch (fuses build_ctx).
// Dynamic smem: As 2*128*36 fp32 | Bs 2*32*132 fp32 = 70656 bytes.
// ---------------------------------------------------------------------------
template <bool CTX>
__device__ __forceinline__ void mma_gemm(const float* __restrict__ A,
                                         const float* __restrict__ A2,
                                         const float* __restrict__ B,
                                         const float* __restrict__ bias,
                                         float* __restrict__ C, int N, int K) {
    extern __shared__ float sg[];
    float* As = sg;            // [2][128][36]
    float* Bs = sg + 2 * 128 * 36;  // [2][32][132]
    const int tid = threadIdx.x;
    const int m0 = blockIdx.y * 128, n0 = blockIdx.x * 128;
    const int lane = tid & 31, wid = tid >> 5;
    const int wm = wid & 1, wn = wid >> 1;
    const int gid = lane >> 2, tig = lane & 3;

    auto loadA = [&](int st, int k0) {
#pragma unroll
        for (int i = 0; i < 4; i++) {
            int idx = tid + i * 256;
            int r = idx >> 3, c4 = (idx & 7) << 2;
            const float* src;
            int m = m0 + r;
            if (CTX) {
                int b = m / NCTX, t = m % NCTX;
                src = (t < ML) ? (A2 + ((size_t)(b * ML + t)) * DIM + k0 + c4)
                               : (A + ((size_t)(b * NQ + t - ML)) * DIM + k0 + c4);
            } else {
                src = A + (size_t)m * K + k0 + c4;
            }
            cpa16(s2u(&As[st * 4608 + r * 36 + c4]), src);
        }
    };
    auto loadB = [&](int st, int k0) {
#pragma unroll
        for (int i = 0; i < 4; i++) {
            int idx = tid + i * 256;
            int r = idx >> 5, c4 = (idx & 31) << 2;
            cpa16(s2u(&Bs[st * 4224 + r * 132 + c4]), B + (size_t)(k0 + r) * N + n0 + c4);
        }
    };

    float acc[4][4][4] = {};
    loadA(0, 0); loadB(0, 0); cpa_commit();
    const int T = K / 32;
    for (int it = 0; it < T; ++it) {
        const int st = it & 1;
        if (it + 1 < T) { loadA(st ^ 1, (it + 1) * 32); loadB(st ^ 1, (it + 1) * 32); }
        cpa_commit();
        cpa_wait<1>();
        __syncthreads();
        const float* Asl = As + st * 4608;
        const float* Bsl = Bs + st * 4224;
#pragma unroll
        for (int kk = 0; kk < 4; kk++) {
            const int kb = kk * 8;
            unsigned a[4][4], bf[4][2];
#pragma unroll
            for (int mt = 0; mt < 4; mt++) {
                int r = wm * 64 + mt * 16 + gid;
                a[mt][0] = f2tf(Asl[r * 36 + kb + tig]);
                a[mt][1] = f2tf(Asl[(r + 8) * 36 + kb + tig]);
                a[mt][2] = f2tf(Asl[r * 36 + kb + tig + 4]);
                a[mt][3] = f2tf(Asl[(r + 8) * 36 + kb + tig + 4]);
            }
#pragma unroll
            for (int nt = 0; nt < 4; nt++) {
                int c = wn * 32 + nt * 8 + gid;
                bf[nt][0] = f2tf(Bsl[(kb + tig) * 132 + c]);
                bf[nt][1] = f2tf(Bsl[(kb + tig + 4) * 132 + c]);
            }
#pragma unroll
            for (int mt = 0; mt < 4; mt++)
#pragma unroll
                for (int nt = 0; nt < 4; nt++) mma8(acc[mt][nt], a[mt], bf[nt]);
        }
        __syncthreads();
    }
#pragma unroll
    for (int mt = 0; mt < 4; mt++) {
        int r0 = m0 + wm * 64 + mt * 16 + gid;
#pragma unroll
        for (int nt = 0; nt < 4; nt++) {
            int c0 = n0 + wn * 32 + nt * 8 + 2 * tig;
            C[(size_t)r0 * N + c0]           = acc[mt][nt][0] + bias[c0];
            C[(size_t)r0 * N + c0 + 1]       = acc[mt][nt][1] + bias[c0 + 1];
            C[(size_t)(r0 + 8) * N + c0]     = acc[mt][nt][2] + bias[c0];
            C[(size_t)(r0 + 8) * N + c0 + 1] = acc[mt][nt][3] + bias[c0 + 1];
        }
    }
}

__global__ void __launch_bounds__(256) gemm_q(const float* x, const float* Wq, const float* bq) {
    mma_gemm<false>(x, nullptr, Wq, bq, g_Q, DIM, DIM);
}
__global__ void __launch_bounds__(256) gemm_kv(const float* x, const float* mem,
                                               const float* Wkv, const float* bkv) {
    mma_gemm<true>(x, mem, Wkv, bkv, g_KV, 2 * DIM, DIM);
}
__global__ void __launch_bounds__(256) gemm_out(const float* Wo, const float* bo, float* out) {
    mma_gemm<false>(g_O, nullptr, Wo, bo, out, DIM, DIM);
}

#define GEMM_SMEM ((2 * 128 * 36 + 2 * 32 * 132) * 4)

// ---------------------------------------------------------------------------
// pos = pos_emb @ Wp (+bp), split-K fp32 (tiny: 2048x64x1024)
// grid (8 k-slices, 32 m-tiles of 64), 256 threads. Partials then reduce.
// ---------------------------------------------------------------------------
__global__ void __launch_bounds__(256) pos_part(const float* __restrict__ pe,
                                                const float* __restrict__ Wp) {
    __shared__ float As[64][129];
    const int m0 = blockIdx.y * 64, k0 = blockIdx.x * 128;
    const int tid = threadIdx.x;
#pragma unroll
    for (int i = 0; i < 8; i++) {
        int idx = tid + i * 256;
        int r = idx >> 5, c4 = (idx & 31) << 2;
        float4 v = *(const float4*)&pe[(size_t)(m0 + r) * DIM + k0 + c4];
        As[r][c4] = v.x; As[r][c4 + 1] = v.y; As[r][c4 + 2] = v.z; As[r][c4 + 3] = v.w;
    }
    __syncthreads();
    const int tx = tid & 63, ty = tid >> 6;
    float acc[16];
#pragma unroll
    for (int i = 0; i < 16; i++) acc[i] = 0.f;
    for (int k = 0; k < 128; k++) {
        float bv = Wp[(size_t)(k0 + k) * DH + tx];
#pragma unroll
        for (int rr = 0; rr < 16; rr++) acc[rr] += As[ty * 16 + rr][k] * bv;
    }
#pragma unroll
    for (int rr = 0; rr < 16; rr++)
        g_PPART[((size_t)blockIdx.x * NQ + m0 + ty * 16 + rr) * DH + tx] = acc[rr];
}

__global__ void __launch_bounds__(256) pos_reduce(const float* __restrict__ bp) {
    int idx = blockIdx.x * 256 + threadIdx.x;  // over NQ*DH/4
    if (idx >= NQ * DH / 4) return;
    float4 acc = make_float4(0.f, 0.f, 0.f, 0.f);
#pragma unroll
    for (int s = 0; s < 8; s++) {
        float4 v = ((const float4*)g_PPART)[s * (NQ * DH / 4) + idx];
        acc.x += v.x; acc.y += v.y; acc.z += v.z; acc.w += v.w;
    }
    int col = (idx << 2) & 63;
    float4 b = *(const float4*)&bp[col];
    ((float4*)g_POS)[idx] = make_float4(acc.x + b.x, acc.y + b.y, acc.z + b.z, acc.w + b.w);
}

// ---------------------------------------------------------------------------
// Flash attention + Transformer-XL relative position, tf32 mma.
// 128 threads (4 warps), 64-row q-tile; Q fragments register-resident.
// 3-buffer cp.async rotation: while QK-mma reads K(jt), V(jt) streams in;
// while PV-mma reads V(jt), K(jt+1) streams in. K/V kept fp32 in smem,
// tf32-converted at fragment load (identical values to R2).
// smem (floats): KB[3][64*68] | PB u32[64*68] | PD[64*132] | em[1024] = 107520 B
// Q staged through PD area before the mainloop.
// ---------------------------------------------------------------------------
#define SQ 68
#define SPD 132
#define KBUF 4352  // 64*68
#define ATTN_SMEM ((3 * KBUF + KBUF + 64 * SPD + 1024) * 4)

__global__ void __launch_bounds__(128) attn_kernel(const float* __restrict__ em) {
    extern __shared__ float smp[];
    float* KB      = smp;                       // 3 x [64][68] fp32 (K/V rotation)
    unsigned* PB   = (unsigned*)(smp + 3 * KBUF);  // [64][68] tf32 (pos tile / P tile)
    float* PD      = smp + 4 * KBUF;            // [64][132] ring (also Q staging)
    float* em_s    = smp + 4 * KBUF + 64 * SPD; // [1024]

    const int bh = blockIdx.y;
    const int b = bh >> 4, h = bh & 15;
    const int qt = 31 - blockIdx.x;
    const int i0 = qt * 64;
    const int tid = threadIdx.x;
    const int lane = tid & 31, wid = tid >> 5;
    const int gid = lane >> 2, tig = lane & 3;
    const int r1 = wid * 16 + gid, r2 = r1 + 8;

    // ---- prolog: issue K(0) cp.async; stage Q; load em ----
#pragma unroll
    for (int i = 0; i < 8; i++) {
        int idx = tid + i * 128;
        int r = idx >> 4, c4 = (idx & 15) << 2;
        cpa16(s2u(&KB[r * SQ + c4]),
              &g_KV[(size_t)(b * NCTX + r) * (2 * DIM) + h * DH + c4]);
    }
    cpa_commit();
    for (int i = tid; i < 1024; i += 128) {
        int r = i >> 4, c4 = (i & 15) << 2;
        float4 q = *(const float4*)&g_Q[(size_t)(b * NQ + i0 + r) * DIM + h * DH + c4];
        q.x *= 0.125f; q.y *= 0.125f; q.z *= 0.125f; q.w *= 0.125f;
        *(float4*)&PD[r * 64 + c4] = q;  // fp32 staging in PD area
    }
    for (int i = tid; i < ML / 4; i += 128)
        ((float4*)em_s)[i] = ((const float4*)(em + b * ML))[i];
    __syncthreads();

    // Q fragments -> registers (scaled, tf32)
    unsigned qa[8][4];
#pragma unroll
    for (int kk = 0; kk < 8; kk++) {
        const int kb = kk * 8;
        qa[kk][0] = f2tf(PD[r1 * 64 + kb + tig]);
        qa[kk][1] = f2tf(PD[r2 * 64 + kb + tig]);
        qa[kk][2] = f2tf(PD[r1 * 64 + kb + tig + 4]);
        qa[kk][3] = f2tf(PD[r2 * 64 + kb + tig + 4]);
    }

    float m1 = -1e30f, m2 = -1e30f, l1 = 0.f, l2 = 0.f;
    float O[8][4] = {};

    const int nT = 17 + qt;
    int Pbase = 0;
    for (int jt = 0; jt < nT; jt++) {
        const int J0 = jt * 64;
        const int kbu = (2 * jt) % 3, vbu = (2 * jt + 1) % 3, nbu = (2 * jt + 2) % 3;
        __syncthreads();  // prev tile's P/V consumed; buffers free

        // ---- issue V(jt) cp.async ----
        float* Vb = KB + vbu * KBUF;
#pragma unroll
        for (int i = 0; i < 8; i++) {
            int idx = tid + i * 128;
            int r = idx >> 4, c4 = (idx & 15) << 2;
            cpa16(s2u(&Vb[r * SQ + c4]),
                  &g_KV[(size_t)(b * NCTX + J0 + r) * (2 * DIM) + DIM + h * DH + c4]);
        }
        cpa_commit();

        // ---- PD ring extension (overlaps K/V transfer) ----
        if (jt >= 16) {
            const int j0l = J0 - ML;
            Pbase = NQ - 64 - i0 + j0l;
            const int nNew = (jt == 16) ? 2 : 1;
            const int Pst = (jt == 16) ? Pbase : Pbase + 64;
            for (int half = 0; half < nNew; half++) {
                const int Pn = Pst + half * 64;
                if (half) __syncthreads();
                for (int i = tid; i < 1024; i += 128) {
                    int s = i >> 4, c4 = (i & 15) << 2;
                    int p = Pn + s;
                    float4 v = make_float4(0.f, 0.f, 0.f, 0.f);
                    if (p < NQ) v = *(const float4*)&g_POS[p * DH + c4];
                    *(uint4*)&PB[s * SQ + c4] =
                        make_uint4(f2tf(v.x), f2tf(v.y), f2tf(v.z), f2tf(v.w));
                }
                __syncthreads();
                float pd[8][4] = {};
#pragma unroll
                for (int kk = 0; kk < 8; kk++) {
                    const int kb = kk * 8;
#pragma unroll
                    for (int nt = 0; nt < 8; nt++) {
                        unsigned bf[2];
                        const int c = nt * 8 + gid;
                        bf[0] = PB[c * SQ + kb + tig];
                        bf[1] = PB[c * SQ + kb + tig + 4];
                        mma8(pd[nt], qa[kk], bf);
                    }
                }
#pragma unroll
                for (int nt = 0; nt < 8; nt++) {
                    const int cb = nt * 8 + 2 * tig;
                    PD[r1 * SPD + ((Pn + cb) & 127)]     = pd[nt][0];
                    PD[r1 * SPD + ((Pn + cb + 1) & 127)] = pd[nt][1];
                    PD[r2 * SPD + ((Pn + cb) & 127)]     = pd[nt][2];
                    PD[r2 * SPD + ((Pn + cb + 1) & 127)] = pd[nt][3];
                }
            }
        }

        cpa_wait<1>();      // K(jt) resident (V(jt) may still be in flight)
        __syncthreads();

        // ---- S = Q K^T ----
        const float* Kb = KB + kbu * KBUF;
        float S[8][4] = {};
#pragma unroll
        for (int kk = 0; kk < 8; kk++) {
            const int kb = kk * 8;
#pragma unroll
            for (int nt = 0; nt < 8; nt++) {
                unsigned bf[2];
                const int c = nt * 8 + gid;
                bf[0] = f2tf(Kb[c * SQ + kb + tig]);
                bf[1] = f2tf(Kb[c * SQ + kb + tig + 4]);
                mma8(S[nt], qa[kk], bf);
            }
        }

        // ---- issue K(jt+1) cp.async ----
        if (jt + 1 < nT) {
            float* Nb = KB + nbu * KBUF;
#pragma unroll
            for (int i = 0; i < 8; i++) {
                int idx = tid + i * 128;
                int r = idx >> 4, c4 = (idx & 15) << 2;
                cpa16(s2u(&Nb[r * SQ + c4]),
                      &g_KV[(size_t)(b * NCTX + J0 + 64 + r) * (2 * DIM) + h * DH + c4]);
            }
        }
        cpa_commit();

        // ---- pos/mask or expire prep ----
        const bool memr = (jt < 16);
        float emv[8][2];
        if (memr) {
#pragma unroll
            for (int nt = 0; nt < 8; nt++) {
                const int cb = nt * 8 + 2 * tig;
                emv[nt][0] = em_s[J0 + cb]; emv[nt][1] = em_s[J0 + cb + 1];
            }
        } else {
            const int j0l = J0 - ML;
#pragma unroll
            for (int nt = 0; nt < 8; nt++) {
                const int cb = nt * 8 + 2 * tig;
                S[nt][0] += PD[r1 * SPD + ((Pbase + 63 + cb - r1) & 127)];
                S[nt][1] += PD[r1 * SPD + ((Pbase + 64 + cb - r1) & 127)];
                S[nt][2] += PD[r2 * SPD + ((Pbase + 63 + cb - r2) & 127)];
                S[nt][3] += PD[r2 * SPD + ((Pbase + 64 + cb - r2) & 127)];
                if (j0l + cb > i0 + r1)     S[nt][0] = -1e10f;
                if (j0l + cb + 1 > i0 + r1) S[nt][1] = -1e10f;
                if (j0l + cb > i0 + r2)     S[nt][2] = -1e10f;
                if (j0l + cb + 1 > i0 + r2) S[nt][3] = -1e10f;
            }
        }

        // ---- online softmax ----
        float mx1 = -1e30f, mx2 = -1e30f;
#pragma unroll
        for (int nt = 0; nt < 8; nt++) {
            mx1 = fmaxf(mx1, fmaxf(S[nt][0], S[nt][1]));
            mx2 = fmaxf(mx2, fmaxf(S[nt][2], S[nt][3]));
        }
        mx1 = fmaxf(mx1, __shfl_xor_sync(0xffffffffu, mx1, 1));
        mx1 = fmaxf(mx1, __shfl_xor_sync(0xffffffffu, mx1, 2));
        mx2 = fmaxf(mx2, __shfl_xor_sync(0xffffffffu, mx2, 1));
        mx2 = fmaxf(mx2, __shfl_xor_sync(0xffffffffu, mx2, 2));
        const float mn1 = fmaxf(m1, mx1), mn2 = fmaxf(m2, mx2);
        const float al1 = __expf(m1 - mn1), al2 = __expf(m2 - mn2);
        float rs1 = 0.f, rs2 = 0.f;
#pragma unroll
        for (int nt = 0; nt < 8; nt++) {
            float e0 = __expf(S[nt][0] - mn1), e1 = __expf(S[nt][1] - mn1);
            float e2 = __expf(S[nt][2] - mn2), e3 = __expf(S[nt][3] - mn2);
            rs1 += e0 + e1; rs2 += e2 + e3;
            if (memr) { e0 *= emv[nt][0]; e1 *= emv[nt][1]; e2 *= emv[nt][0]; e3 *= emv[nt][1]; }
            const int cb = nt * 8 + 2 * tig;
            PB[r1 * SQ + cb] = f2tf(e0); PB[r1 * SQ + cb + 1] = f2tf(e1);
            PB[r2 * SQ + cb] = f2tf(e2); PB[r2 * SQ + cb + 1] = f2tf(e3);
        }
        rs1 += __shfl_xor_sync(0xffffffffu, rs1, 1);
        rs1 += __shfl_xor_sync(0xffffffffu, rs1, 2);
        rs2 += __shfl_xor_sync(0xffffffffu, rs2, 1);
        rs2 += __shfl_xor_sync(0xffffffffu, rs2, 2);
        m1 = mn1; m2 = mn2;
        l1 = l1 * al1 + rs1; l2 = l2 * al2 + rs2;
#pragma unroll
        for (int nt = 0; nt < 8; nt++) {
            O[nt][0] *= al1; O[nt][1] *= al1; O[nt][2] *= al2; O[nt][3] *= al2;
        }

        cpa_wait<1>();      // V(jt) resident (K(jt+1) may still be in flight)
        __syncthreads();    // P published, V ready

        // ---- O += P @ V ----
#pragma unroll
        for (int kk = 0; kk < 8; kk++) {
            const int kb = kk * 8;
            unsigned a[4];
            a[0] = PB[r1 * SQ + kb + tig];     a[1] = PB[r2 * SQ + kb + tig];
            a[2] = PB[r1 * SQ + kb + tig + 4]; a[3] = PB[r2 * SQ + kb + tig + 4];
#pragma unroll
            for (int nt = 0; nt < 8; nt++) {
                unsigned bf[2];
                const int c = nt * 8 + gid;
                bf[0] = f2tf(Vb[(kb + tig) * SQ + c]);
                bf[1] = f2tf(Vb[(kb + tig + 4) * SQ + c]);
                mma8(O[nt], a, bf);
            }
        }
    }

    // ---- finalize ----
    const float inv1 = 1.f / l1, inv2 = 1.f / l2;
#pragma unroll
    for (int nt = 0; nt < 8; nt++) {
        const int d = h * DH + nt * 8 + 2 * tig;
        float* o1 = &g_O[(size_t)(b * NQ + i0 + r1) * DIM + d];
        float* o2 = &g_O[(size_t)(b * NQ + i0 + r2) * DIM + d];
        o1[0] = O[nt][0] * inv1; o1[1] = O[nt][1] * inv1;
        o2[0] = O[nt][2] * inv2; o2[1] = O[nt][3] * inv2;
    }
}

// ---------------------------------------------------------------------------
extern "C" void kernel_launch(void* const* d_in, const int* in_sizes, int n_in,
                              void* d_out, int out_size) {
    const float* x   = (const float*)d_in[0];
    const float* pe  = (const float*)d_in[1];
    const float* mem = (const float*)d_in[2];
    const float* em  = (const float*)d_in[3];
    const float* Wq  = (const float*)d_in[4];
    const float* bq  = (const float*)d_in[5];
    const float* Wkv = (const float*)d_in[6];
    const float* bkv = (const float*)d_in[7];
    const float* Wo  = (const float*)d_in[8];
    const float* bo  = (const float*)d_in[9];
    const float* Wp  = (const float*)d_in[10];
    const float* bp  = (const float*)d_in[11];
    float* out = (float*)d_out;

    cudaFuncSetAttribute(gemm_q, cudaFuncAttributeMaxDynamicSharedMemorySize, GEMM_SMEM);
    cudaFuncSetAttribute(gemm_kv, cudaFuncAttributeMaxDynamicSharedMemorySize, GEMM_SMEM);
    cudaFuncSetAttribute(gemm_out, cudaFuncAttributeMaxDynamicSharedMemorySize, GEMM_SMEM);
    cudaFuncSetAttribute(attn_kernel, cudaFuncAttributeMaxDynamicSharedMemorySize, ATTN_SMEM);

    gemm_q<<<dim3(8, 32), 256, GEMM_SMEM>>>(x, Wq, bq);
    gemm_kv<<<dim3(16, 48), 256, GEMM_SMEM>>>(x, mem, Wkv, bkv);
    pos_part<<<dim3(8, 32), 256>>>(pe, Wp);
    pos_reduce<<<128, 256>>>(bp);
    attn_kernel<<<dim3(32, 32), 128, ATTN_SMEM>>>(em);
    gemm_out<<<dim3(8, 32), 256, GEMM_SMEM>>>(Wo, bo, out);
}